// round 6
// baseline (speedup 1.0000x reference)
#include <cuda_runtime.h>
#include <math.h>

#define NN 100000
#define EE 1600000
#define CC 128
#define HH 64
#define GG 512
#define KMAX 32

// ---------------- scratch (device globals: allocation-free) ----------------
__device__ float4 g_agg1[NN * (CC / 4)];   // zeroed only at kept rows
__device__ float4 g_out1[NN * (HH / 4)];   // written only at kept rows
__device__ float4 g_agg2[NN * (HH / 4)];   // zeroed only at kept rows
__device__ float g_score[NN];              // written only at kept rows
__device__ unsigned char g_mask[NN];
__device__ float g_klval[GG];
__device__ float g_cntval[GG];
__device__ int g_kept[GG * KMAX];
__device__ int g_keptcnt[GG];
__device__ int g_elist[EE];
__device__ int g_n2;
__device__ int g_d1;

// ---------------- helpers ----------------
__device__ __forceinline__ void red_add_v4(float4* a, float4 v) {
    asm volatile("red.global.add.v4.f32 [%0], {%1,%2,%3,%4};"
                 :: "l"(a), "f"(v.x), "f"(v.y), "f"(v.z), "f"(v.w) : "memory");
}
// L1-bypassing load (for intra-kernel cross-block reads after threadfence)
__device__ __forceinline__ float4 ldcg4(const float4* p) {
    float4 r;
    asm volatile("ld.global.cg.v4.f32 {%0,%1,%2,%3}, [%4];"
                 : "=f"(r.x), "=f"(r.y), "=f"(r.z), "=f"(r.w) : "l"(p));
    return r;
}

// ---------------- k_pool: fused raw-score + per-graph softmax/topk ----------
// One block per graph (batch sorted -> contiguous segment via binary search).
__global__ void k_pool(const float4* __restrict__ x4, const float4* __restrict__ pw4,
                       const int* __restrict__ batch, const float* __restrict__ attn) {
    int b = blockIdx.x;
    int t = threadIdx.x;
    __shared__ float sraw[1024];
    __shared__ float red[256];
    __shared__ int s_se[2];
    __shared__ int s_kcnt;
    if (t == 0) s_kcnt = 0;
    if (b == 0 && t == 0) { g_n2 = 0; g_d1 = 0; }
    if (t < 2) {
        int target = b + t;
        int lo = 0, hi = NN;
        while (lo < hi) { int mid = (lo + hi) >> 1; if (batch[mid] < target) lo = mid + 1; else hi = mid; }
        s_se[t] = lo;
    }
    __syncthreads();
    int start = s_se[0];
    int len = s_se[1] - start;   // ~195, far below 1024

    // raw dot: one warp per node
    int wid = t >> 5, lane = t & 31;
    float4 w = pw4[lane];
    for (int i = wid; i < len; i += 8) {
        float4 v = x4[(size_t)(start + i) * 32 + lane];
        float s = v.x * w.x + v.y * w.y + v.z * w.z + v.w * w.w;
        #pragma unroll
        for (int o = 16; o; o >>= 1) s += __shfl_down_sync(0xffffffffu, s, o);
        if (lane == 0) sraw[i] = s;
    }
    __syncthreads();

    // max
    float m = -INFINITY;
    for (int i = t; i < len; i += 256) m = fmaxf(m, sraw[i]);
    red[t] = m; __syncthreads();
    for (int o = 128; o; o >>= 1) { if (t < o) red[t] = fmaxf(red[t], red[t + o]); __syncthreads(); }
    m = red[0]; __syncthreads();

    // sum of e
    float sum = 0.f;
    for (int i = t; i < len; i += 256) sum += expf(sraw[i] - m);
    red[t] = sum; __syncthreads();
    for (int o = 128; o; o >>= 1) { if (t < o) red[t] += red[t + o]; __syncthreads(); }
    float z = red[0]; __syncthreads();

    // smax = score of argmax node = exp(0)/z = 1/z (bitwise identical to ref's max)
    float smax = 1.0f / z;
    float thresh = fminf(smax - 1e-7f, 0.05f);

    // mask, kept list, KL, cnt, zero agg rows for kept
    float kl = 0.f, cnt = 0.f;
    for (int i = t; i < len; i += 256) {
        float s = expf(sraw[i] - m) / z;
        int node = start + i;
        bool keep = s > thresh;
        g_mask[node] = keep ? 1 : 0;
        if (keep) {
            cnt += 1.f;
            float a = attn[node];
            kl += a * (logf(a) - logf(s + 1e-14f));
            g_score[node] = s;
            int slot = atomicAdd(&s_kcnt, 1);
            if (slot < KMAX) g_kept[b * KMAX + slot] = node;
            float4 zz = make_float4(0.f, 0.f, 0.f, 0.f);
            float4* a1 = &g_agg1[(size_t)node * 32];
            #pragma unroll
            for (int q = 0; q < 32; q++) a1[q] = zz;
            float4* a2 = &g_agg2[(size_t)node * 16];
            #pragma unroll
            for (int q = 0; q < 16; q++) a2[q] = zz;
        }
    }
    red[t] = kl; __syncthreads();
    for (int o = 128; o; o >>= 1) { if (t < o) red[t] += red[t + o]; __syncthreads(); }
    if (t == 0) g_klval[b] = red[0];
    __syncthreads();
    red[t] = cnt; __syncthreads();
    for (int o = 128; o; o >>= 1) { if (t < o) red[t] += red[t + o]; __syncthreads(); }
    if (t == 0) {
        g_cntval[b] = red[0];
        g_keptcnt[b] = (s_kcnt < KMAX) ? s_kcnt : KMAX;
    }
}

// ---------------- k_edges: scatter-1 + both-kept edge list + ratio ----------
#define EPB 1024
__global__ void k_edges(const int* __restrict__ ei, const float4* __restrict__ x4,
                        float* __restrict__ out) {
    __shared__ int list[EPB];
    __shared__ int scnt;
    __shared__ float rsum[256];
    if (threadIdx.x == 0) scnt = 0;
    __syncthreads();
    int q = blockIdx.x * 256 + threadIdx.x;
    if (q < EE / 4) {
        int4 d4 = ((const int4*)(ei + EE))[q];
        int e0 = q * 4;
        int dd[4] = {d4.x, d4.y, d4.z, d4.w};
        #pragma unroll
        for (int k = 0; k < 4; k++) {
            int d = dd[k];
            if (g_mask[d]) {
                int e = e0 + k;
                int p = atomicAdd(&scnt, 1);
                list[p] = e;
                int s = ei[e];
                if (g_mask[s]) {
                    int w = atomicAdd(&g_n2, 1);
                    g_elist[w] = e;
                }
            }
        }
    }
    __syncthreads();
    int nk = scnt;
    int wid = threadIdx.x >> 5;
    int lane = threadIdx.x & 31;
    for (int i = wid; i < nk; i += 8) {
        int ee = list[i];
        int s = ei[ee];
        int d = ei[EE + ee];
        red_add_v4(&g_agg1[(size_t)d * 32 + lane], x4[(size_t)s * 32 + lane]);
    }
    // block 0 also computes ratio (g_cntval ready since k_pool)
    if (blockIdx.x == 0) {
        __syncthreads();
        rsum[threadIdx.x] = g_cntval[threadIdx.x] + g_cntval[threadIdx.x + 256];
        __syncthreads();
        for (int o = 128; o; o >>= 1) { if (threadIdx.x < o) rsum[threadIdx.x] += rsum[threadIdx.x + o]; __syncthreads(); }
        if (threadIdx.x == 0) out[2 * GG] = rsum[0] / (float)NN;
    }
}

// ---------------- k_gin1: warp-per-graph MLP (no smem), tail does scatter-2 --
__global__ void k_gin1(const float* __restrict__ x,
                       const float* __restrict__ W1, const float* __restrict__ b1,
                       const float* __restrict__ W2, const float* __restrict__ b2,
                       const int* __restrict__ ei) {
    int t = threadIdx.x;
    int wid = t >> 5, lane = t & 31;
    int g = blockIdx.x * 8 + wid;        // grid 64 * 8 warps = 512 graphs exactly
    int cnt = g_keptcnt[g];
    float2 bb1 = __ldg((const float2*)b1 + lane);
    float2 bb2 = __ldg((const float2*)b2 + lane);

    for (int s = 0; s < cnt; s++) {
        int n = g_kept[g * KMAX + s];
        float4 xv = ((const float4*)x)[(size_t)n * 32 + lane];
        float4 av = g_agg1[(size_t)n * 32 + lane];
        float4 v = make_float4(xv.x + av.x, xv.y + av.y, xv.z + av.z, xv.w + av.w);

        // layer 1: out j = 2*lane, 2*lane+1
        float acc0 = bb1.x, acc1 = bb1.y;
        #pragma unroll 4
        for (int qq = 0; qq < 32; qq++) {
            float x0 = __shfl_sync(0xffffffffu, v.x, qq);
            float x1 = __shfl_sync(0xffffffffu, v.y, qq);
            float x2 = __shfl_sync(0xffffffffu, v.z, qq);
            float x3 = __shfl_sync(0xffffffffu, v.w, qq);
            const float2* wr = (const float2*)(W1 + (size_t)(4 * qq) * HH) + lane;
            float2 w0 = __ldg(wr);
            float2 w1 = __ldg(wr + 32);
            float2 w2 = __ldg(wr + 64);
            float2 w3 = __ldg(wr + 96);
            acc0 = fmaf(x0, w0.x, acc0); acc1 = fmaf(x0, w0.y, acc1);
            acc0 = fmaf(x1, w1.x, acc0); acc1 = fmaf(x1, w1.y, acc1);
            acc0 = fmaf(x2, w2.x, acc0); acc1 = fmaf(x2, w2.y, acc1);
            acc0 = fmaf(x3, w3.x, acc0); acc1 = fmaf(x3, w3.y, acc1);
        }
        float st0 = fmaxf(acc0, 0.f), st1 = fmaxf(acc1, 0.f);

        // layer 2: hidden k distributed as k=2m (st0@m), k=2m+1 (st1@m)
        float o0 = bb2.x, o1 = bb2.y;
        #pragma unroll 4
        for (int mm = 0; mm < 32; mm++) {
            float xa = __shfl_sync(0xffffffffu, st0, mm);
            float xb = __shfl_sync(0xffffffffu, st1, mm);
            const float2* wr = (const float2*)(W2 + (size_t)(2 * mm) * HH) + lane;
            float2 wa = __ldg(wr);
            float2 wb = __ldg(wr + 32);
            o0 = fmaf(xa, wa.x, o0); o1 = fmaf(xa, wa.y, o1);
            o0 = fmaf(xb, wb.x, o0); o1 = fmaf(xb, wb.y, o1);
        }
        float sc = g_score[n];
        float2 res = make_float2(fmaxf(o0, 0.f) * sc, fmaxf(o1, 0.f) * sc);
        ((float2*)&g_out1[(size_t)n * 16])[lane] = res;
    }

    // tail: last block to finish performs scatter-2 (needs all out1 rows)
    __syncthreads();
    __threadfence();
    __shared__ int s_tkt;
    if (t == 0) s_tkt = atomicAdd(&g_d1, 1);
    __syncthreads();
    if (s_tkt == (int)gridDim.x - 1) {
        int n2 = g_n2;
        for (int i = wid; i < n2; i += 8) {
            int e = g_elist[i];
            int ss = ei[e];
            int dd = ei[EE + e];
            if (lane < 16) {
                float4 v = ldcg4(&g_out1[(size_t)ss * 16 + lane]);
                red_add_v4(&g_agg2[(size_t)dd * 16 + lane], v);
            }
        }
    }
}

// ---------------- k_gin2: warp-per-graph MLP + fused pooling/pred/loss ------
__global__ void k_gin2(const float* __restrict__ W3, const float* __restrict__ b3,
                       const float* __restrict__ W4, const float* __restrict__ b4,
                       const float* __restrict__ Wl, const float* __restrict__ bl,
                       float* __restrict__ out) {
    int t = threadIdx.x;
    int wid = t >> 5, lane = t & 31;
    int g = blockIdx.x * 8 + wid;
    int cnt = g_keptcnt[g];
    float2 bb3 = __ldg((const float2*)b3 + lane);
    float2 bb4 = __ldg((const float2*)b4 + lane);
    float go0 = 0.f, go1 = 0.f;

    for (int s = 0; s < cnt; s++) {
        int n = g_kept[g * KMAX + s];
        float2 ov = ((const float2*)&g_out1[(size_t)n * 16])[lane];
        float2 av = ((const float2*)&g_agg2[(size_t)n * 16])[lane];
        float in0 = ov.x + av.x, in1 = ov.y + av.y;

        float acc0 = bb3.x, acc1 = bb3.y;
        #pragma unroll 4
        for (int mm = 0; mm < 32; mm++) {
            float xa = __shfl_sync(0xffffffffu, in0, mm);
            float xb = __shfl_sync(0xffffffffu, in1, mm);
            const float2* wr = (const float2*)(W3 + (size_t)(2 * mm) * HH) + lane;
            float2 wa = __ldg(wr);
            float2 wb = __ldg(wr + 32);
            acc0 = fmaf(xa, wa.x, acc0); acc1 = fmaf(xa, wa.y, acc1);
            acc0 = fmaf(xb, wb.x, acc0); acc1 = fmaf(xb, wb.y, acc1);
        }
        float st0 = fmaxf(acc0, 0.f), st1 = fmaxf(acc1, 0.f);

        float o0 = bb4.x, o1 = bb4.y;
        #pragma unroll 4
        for (int mm = 0; mm < 32; mm++) {
            float xa = __shfl_sync(0xffffffffu, st0, mm);
            float xb = __shfl_sync(0xffffffffu, st1, mm);
            const float2* wr = (const float2*)(W4 + (size_t)(2 * mm) * HH) + lane;
            float2 wa = __ldg(wr);
            float2 wb = __ldg(wr + 32);
            o0 = fmaf(xa, wa.x, o0); o1 = fmaf(xa, wa.y, o1);
            o0 = fmaf(xb, wb.x, o0); o1 = fmaf(xb, wb.y, o1);
        }
        go0 += fmaxf(o0, 0.f);
        go1 += fmaxf(o1, 0.f);
    }

    // pred + attn_loss for this graph
    float2 wl = __ldg((const float2*)Wl + lane);
    float p = go0 * wl.x + go1 * wl.y;
    #pragma unroll
    for (int o = 16; o; o >>= 1) p += __shfl_down_sync(0xffffffffu, p, o);
    if (lane == 0) {
        out[g] = p + bl[0];
        out[GG + g] = g_klval[g] / fmaxf(g_cntval[g], 1.0f);
    }
}

// ---------------- launch ----------------
extern "C" void kernel_launch(void* const* d_in, const int* in_sizes, int n_in,
                              void* d_out, int out_size) {
    const float* x      = (const float*)d_in[0];
    const int*   ei     = (const int*)d_in[1];
    const int*   batch  = (const int*)d_in[2];
    const float* attn   = (const float*)d_in[3];
    const float* W1     = (const float*)d_in[4];
    const float* b1     = (const float*)d_in[5];
    const float* W2     = (const float*)d_in[6];
    const float* b2     = (const float*)d_in[7];
    const float* pool_w = (const float*)d_in[8];
    const float* W3     = (const float*)d_in[9];
    const float* b3     = (const float*)d_in[10];
    const float* W4     = (const float*)d_in[11];
    const float* b4     = (const float*)d_in[12];
    const float* Wl     = (const float*)d_in[13];
    const float* bl     = (const float*)d_in[14];
    float* out = (float*)d_out;

    k_pool<<<GG, 256>>>((const float4*)x, (const float4*)pool_w, batch, attn);
    k_edges<<<(EE + EPB - 1) / EPB, 256>>>(ei, (const float4*)x, out);
    k_gin1<<<64, 256>>>(x, W1, b1, W2, b2, ei);
    k_gin2<<<64, 256>>>(W3, b3, W4, b4, Wl, bl, out);
}

// round 7
// speedup vs baseline: 1.4768x; 1.4768x over previous
#include <cuda_runtime.h>
#include <math.h>

#define NN 100000
#define EE 1600000
#define CC 128
#define HH 64
#define GG 512
#define KMAX 32

// ---------------- scratch (device globals: allocation-free) ----------------
__device__ float4 g_agg1[NN * (CC / 4)];   // zeroed only at kept rows
__device__ float4 g_out1[NN * (HH / 4)];   // written only at kept rows
__device__ float4 g_agg2[NN * (HH / 4)];   // zeroed only at kept rows
__device__ float g_score[NN];              // written only at kept rows
__device__ unsigned char g_mask[NN];
__device__ float g_klval[GG];
__device__ float g_cntval[GG];
__device__ int g_kept[GG * KMAX];
__device__ int g_keptcnt[GG];
__device__ int g_elist[EE];
__device__ int g_n2;
__device__ int g_c1;
__device__ int g_c2;

// ---------------- helpers ----------------
__device__ __forceinline__ void red_add_v4(float4* a, float4 v) {
    asm volatile("red.global.add.v4.f32 [%0], {%1,%2,%3,%4};"
                 :: "l"(a), "f"(v.x), "f"(v.y), "f"(v.z), "f"(v.w) : "memory");
}
__device__ __forceinline__ float4 ldcg4(const float4* p) {
    float4 r;
    asm volatile("ld.global.cg.v4.f32 {%0,%1,%2,%3}, [%4];"
                 : "=f"(r.x), "=f"(r.y), "=f"(r.z), "=f"(r.w) : "l"(p));
    return r;
}
__device__ __forceinline__ float ldcg(const float* p) {
    float r;
    asm volatile("ld.global.cg.f32 %0, [%1];" : "=f"(r) : "l"(p));
    return r;
}

// ---------------- k_pool: fused raw-score + per-graph softmax/topk ----------
__global__ void k_pool(const float4* __restrict__ x4, const float4* __restrict__ pw4,
                       const int* __restrict__ batch, const float* __restrict__ attn) {
    int b = blockIdx.x;
    int t = threadIdx.x;
    __shared__ float sraw[1024];
    __shared__ float red[256];
    __shared__ int s_se[2];
    __shared__ int s_kcnt;
    if (t == 0) s_kcnt = 0;
    if (b == 0 && t == 0) { g_n2 = 0; g_c1 = 0; g_c2 = 0; }
    if (t < 2) {
        int target = b + t;
        int lo = 0, hi = NN;
        while (lo < hi) { int mid = (lo + hi) >> 1; if (batch[mid] < target) lo = mid + 1; else hi = mid; }
        s_se[t] = lo;
    }
    __syncthreads();
    int start = s_se[0];
    int len = s_se[1] - start;

    int wid = t >> 5, lane = t & 31;
    float4 w = pw4[lane];
    for (int i = wid; i < len; i += 8) {
        float4 v = x4[(size_t)(start + i) * 32 + lane];
        float s = v.x * w.x + v.y * w.y + v.z * w.z + v.w * w.w;
        #pragma unroll
        for (int o = 16; o; o >>= 1) s += __shfl_down_sync(0xffffffffu, s, o);
        if (lane == 0) sraw[i] = s;
    }
    __syncthreads();

    float m = -INFINITY;
    for (int i = t; i < len; i += 256) m = fmaxf(m, sraw[i]);
    red[t] = m; __syncthreads();
    for (int o = 128; o; o >>= 1) { if (t < o) red[t] = fmaxf(red[t], red[t + o]); __syncthreads(); }
    m = red[0]; __syncthreads();

    float sum = 0.f;
    for (int i = t; i < len; i += 256) sum += expf(sraw[i] - m);
    red[t] = sum; __syncthreads();
    for (int o = 128; o; o >>= 1) { if (t < o) red[t] += red[t + o]; __syncthreads(); }
    float z = red[0]; __syncthreads();

    float smax = 1.0f / z;   // score of the argmax node (exp(0)/z)
    float thresh = fminf(smax - 1e-7f, 0.05f);

    float kl = 0.f, cnt = 0.f;
    for (int i = t; i < len; i += 256) {
        float s = expf(sraw[i] - m) / z;
        int node = start + i;
        bool keep = s > thresh;
        g_mask[node] = keep ? 1 : 0;
        if (keep) {
            cnt += 1.f;
            float a = attn[node];
            kl += a * (logf(a) - logf(s + 1e-14f));
            g_score[node] = s;
            int slot = atomicAdd(&s_kcnt, 1);
            if (slot < KMAX) g_kept[b * KMAX + slot] = node;
            float4 zz = make_float4(0.f, 0.f, 0.f, 0.f);
            float4* a1 = &g_agg1[(size_t)node * 32];
            #pragma unroll
            for (int q = 0; q < 32; q++) a1[q] = zz;
            float4* a2 = &g_agg2[(size_t)node * 16];
            #pragma unroll
            for (int q = 0; q < 16; q++) a2[q] = zz;
        }
    }
    red[t] = kl; __syncthreads();
    for (int o = 128; o; o >>= 1) { if (t < o) red[t] += red[t + o]; __syncthreads(); }
    if (t == 0) g_klval[b] = red[0];
    __syncthreads();
    red[t] = cnt; __syncthreads();
    for (int o = 128; o; o >>= 1) { if (t < o) red[t] += red[t + o]; __syncthreads(); }
    if (t == 0) {
        g_cntval[b] = red[0];
        g_keptcnt[b] = (s_kcnt < KMAX) ? s_kcnt : KMAX;
    }
}

// ---------------- k_edges: scatter-1 + both-kept edge list + ratio ----------
#define EPB 1024
__global__ void k_edges(const int* __restrict__ ei, const float4* __restrict__ x4,
                        float* __restrict__ out) {
    __shared__ int list[EPB];
    __shared__ int scnt;
    __shared__ float rsum[256];
    if (threadIdx.x == 0) scnt = 0;
    __syncthreads();
    int q = blockIdx.x * 256 + threadIdx.x;
    if (q < EE / 4) {
        int4 d4 = ((const int4*)(ei + EE))[q];
        int e0 = q * 4;
        int dd[4] = {d4.x, d4.y, d4.z, d4.w};
        #pragma unroll
        for (int k = 0; k < 4; k++) {
            int d = dd[k];
            if (g_mask[d]) {
                int e = e0 + k;
                int p = atomicAdd(&scnt, 1);
                list[p] = e;
                int s = ei[e];
                if (g_mask[s]) {
                    int w = atomicAdd(&g_n2, 1);
                    g_elist[w] = e;
                }
            }
        }
    }
    __syncthreads();
    int nk = scnt;
    int wid = threadIdx.x >> 5;
    int lane = threadIdx.x & 31;
    for (int i = wid; i < nk; i += 8) {
        int ee = list[i];
        int s = ei[ee];
        int d = ei[EE + ee];
        red_add_v4(&g_agg1[(size_t)d * 32 + lane], x4[(size_t)s * 32 + lane]);
    }
    if (blockIdx.x == 0) {
        __syncthreads();
        rsum[threadIdx.x] = g_cntval[threadIdx.x] + g_cntval[threadIdx.x + 256];
        __syncthreads();
        for (int o = 128; o; o >>= 1) { if (threadIdx.x < o) rsum[threadIdx.x] += rsum[threadIdx.x + o]; __syncthreads(); }
        if (threadIdx.x == 0) out[2 * GG] = rsum[0] / (float)NN;
    }
}

// ---------------- k_tail: gin1 -> barrier -> scatter2 -> barrier -> gin2+out --
// One block per graph, 128 threads per block; all 512 blocks co-resident
// (128 thr, ~2 KB smem), so device-wide spin barriers are safe.
__global__ void __launch_bounds__(128, 4) k_tail(
    const float* __restrict__ x,
    const float* __restrict__ W1, const float* __restrict__ b1,
    const float* __restrict__ W2, const float* __restrict__ b2,
    const int* __restrict__ ei,
    const float* __restrict__ W3, const float* __restrict__ b3,
    const float* __restrict__ W4, const float* __restrict__ b4,
    const float* __restrict__ Wl, const float* __restrict__ bl,
    float* __restrict__ out)
{
    int g = blockIdx.x;
    int t = threadIdx.x;
    int j = t & 63;
    int h = t >> 6;       // k-half: 0 or 1
    __shared__ float sv[CC];
    __shared__ float sp[2][HH];
    __shared__ float sh1[HH];
    __shared__ float sgo[HH];
    int cnt = g_keptcnt[g];

    // ---- Phase 1: GIN1 for this graph's kept nodes ----
    for (int s = 0; s < cnt; s++) {
        int n = g_kept[g * KMAX + s];
        sv[t] = x[(size_t)n * CC + t] + ((const float*)g_agg1)[(size_t)n * CC + t];
        __syncthreads();
        float acc = (h == 0) ? b1[j] : 0.f;
        const float* wp = W1 + (size_t)(h * 64) * HH + j;
        #pragma unroll 8
        for (int k = 0; k < 64; k++) acc = fmaf(sv[h * 64 + k], wp[(size_t)k * HH], acc);
        sp[h][j] = acc;
        __syncthreads();
        if (t < HH) sh1[t] = fmaxf(sp[0][t] + sp[1][t], 0.f);
        __syncthreads();
        float acc2 = (h == 0) ? b2[j] : 0.f;
        const float* wp2 = W2 + (size_t)(h * 32) * HH + j;
        #pragma unroll 8
        for (int k = 0; k < 32; k++) acc2 = fmaf(sh1[h * 32 + k], wp2[(size_t)k * HH], acc2);
        sp[h][j] = acc2;
        __syncthreads();
        if (t < HH)
            ((float*)g_out1)[(size_t)n * HH + t] = fmaxf(sp[0][t] + sp[1][t], 0.f) * g_score[n];
        __syncthreads();
    }

    // ---- device-wide barrier 1 ----
    __threadfence();
    __syncthreads();
    if (t == 0) {
        atomicAdd(&g_c1, 1);
        while (atomicAdd(&g_c1, 0) < (int)gridDim.x) __nanosleep(64);
    }
    __syncthreads();

    // ---- Phase 2: scatter-2 over both-kept edges, spread across all blocks ----
    {
        int n2 = g_n2;
        int wid = t >> 5, lane = t & 31;
        for (int i = blockIdx.x * 4 + wid; i < n2; i += gridDim.x * 4) {
            int e = g_elist[i];
            int ss = ei[e];
            int dd = ei[EE + e];
            if (lane < 16) {
                float4 v = ldcg4(&g_out1[(size_t)ss * 16 + lane]);
                red_add_v4(&g_agg2[(size_t)dd * 16 + lane], v);
            }
        }
    }

    // ---- device-wide barrier 2 ----
    __threadfence();
    __syncthreads();
    if (t == 0) {
        atomicAdd(&g_c2, 1);
        while (atomicAdd(&g_c2, 0) < (int)gridDim.x) __nanosleep(64);
    }
    __syncthreads();

    // ---- Phase 3: GIN2 + global_add_pool + pred + attn_loss ----
    if (t < HH) sgo[t] = 0.f;
    __syncthreads();
    for (int s = 0; s < cnt; s++) {
        int n = g_kept[g * KMAX + s];
        if (t < HH)
            sv[t] = ldcg(&((const float*)g_out1)[(size_t)n * HH + t])
                  + ldcg(&((const float*)g_agg2)[(size_t)n * HH + t]);
        __syncthreads();
        float acc = (h == 0) ? b3[j] : 0.f;
        const float* wp = W3 + (size_t)(h * 32) * HH + j;
        #pragma unroll 8
        for (int k = 0; k < 32; k++) acc = fmaf(sv[h * 32 + k], wp[(size_t)k * HH], acc);
        sp[h][j] = acc;
        __syncthreads();
        if (t < HH) sh1[t] = fmaxf(sp[0][t] + sp[1][t], 0.f);
        __syncthreads();
        float acc2 = (h == 0) ? b4[j] : 0.f;
        const float* wp2 = W4 + (size_t)(h * 32) * HH + j;
        #pragma unroll 8
        for (int k = 0; k < 32; k++) acc2 = fmaf(sh1[h * 32 + k], wp2[(size_t)k * HH], acc2);
        sp[h][j] = acc2;
        __syncthreads();
        if (t < HH) sgo[t] += fmaxf(sp[0][t] + sp[1][t], 0.f);
        __syncthreads();
    }
    if (t < HH) sp[0][t] = sgo[t] * Wl[t];
    __syncthreads();
    if (t < 32) {
        float p = sp[0][t] + sp[0][t + 32];
        #pragma unroll
        for (int o = 16; o; o >>= 1) p += __shfl_down_sync(0xffffffffu, p, o);
        if (t == 0) {
            out[g] = p + bl[0];
            out[GG + g] = g_klval[g] / fmaxf(g_cntval[g], 1.0f);
        }
    }
}

// ---------------- launch ----------------
extern "C" void kernel_launch(void* const* d_in, const int* in_sizes, int n_in,
                              void* d_out, int out_size) {
    const float* x      = (const float*)d_in[0];
    const int*   ei     = (const int*)d_in[1];
    const int*   batch  = (const int*)d_in[2];
    const float* attn   = (const float*)d_in[3];
    const float* W1     = (const float*)d_in[4];
    const float* b1     = (const float*)d_in[5];
    const float* W2     = (const float*)d_in[6];
    const float* b2     = (const float*)d_in[7];
    const float* pool_w = (const float*)d_in[8];
    const float* W3     = (const float*)d_in[9];
    const float* b3     = (const float*)d_in[10];
    const float* W4     = (const float*)d_in[11];
    const float* b4     = (const float*)d_in[12];
    const float* Wl     = (const float*)d_in[13];
    const float* bl     = (const float*)d_in[14];
    float* out = (float*)d_out;

    k_pool<<<GG, 256>>>((const float4*)x, (const float4*)pool_w, batch, attn);
    k_edges<<<(EE + EPB - 1) / EPB, 256>>>(ei, (const float4*)x, out);
    k_tail<<<GG, 128>>>(x, W1, b1, W2, b2, ei, W3, b3, W4, b4, Wl, bl, out);
}

// round 8
// speedup vs baseline: 1.4933x; 1.0112x over previous
#include <cuda_runtime.h>
#include <math.h>

#define NN 100000
#define EE 1600000
#define CC 128
#define HH 64
#define GG 512
#define KMAX 32

// ---------------- scratch (device globals: allocation-free) ----------------
__device__ float4 g_agg1[NN * (CC / 4)];   // zeroed only at kept rows
__device__ float4 g_out1[NN * (HH / 4)];   // written only at kept rows
__device__ float4 g_agg2[NN * (HH / 4)];   // zeroed only at kept rows
__device__ float g_score[NN];              // written only at kept rows
__device__ unsigned int g_bits[(NN + 31) / 32];  // kept bitmask; zero-init, self-cleaning
__device__ float g_klval[GG];
__device__ float g_cntval[GG];
__device__ int g_kept[GG * KMAX];
__device__ int g_keptcnt[GG];
__device__ int g_elist[EE];
__device__ int g_n2;
__device__ int g_c1;
__device__ int g_c2;

// ---------------- helpers ----------------
__device__ __forceinline__ void red_add_v4(float4* a, float4 v) {
    asm volatile("red.global.add.v4.f32 [%0], {%1,%2,%3,%4};"
                 :: "l"(a), "f"(v.x), "f"(v.y), "f"(v.z), "f"(v.w) : "memory");
}
__device__ __forceinline__ float4 ldcg4(const float4* p) {
    float4 r;
    asm volatile("ld.global.cg.v4.f32 {%0,%1,%2,%3}, [%4];"
                 : "=f"(r.x), "=f"(r.y), "=f"(r.z), "=f"(r.w) : "l"(p));
    return r;
}
__device__ __forceinline__ float ldcg(const float* p) {
    float r;
    asm volatile("ld.global.cg.f32 %0, [%1];" : "=f"(r) : "l"(p));
    return r;
}
__device__ __forceinline__ bool testbit(int n) {
    return (__ldg(&g_bits[n >> 5]) >> (n & 31)) & 1u;
}

// ---------------- k_pool: fused raw-score + per-graph softmax/topk ----------
__global__ void k_pool(const float4* __restrict__ x4, const float4* __restrict__ pw4,
                       const int* __restrict__ batch, const float* __restrict__ attn) {
    int b = blockIdx.x;
    int t = threadIdx.x;
    __shared__ float sraw[1024];
    __shared__ float red[256];
    __shared__ int s_se[2];
    __shared__ int s_kcnt;
    if (t == 0) s_kcnt = 0;
    if (b == 0 && t == 0) { g_n2 = 0; g_c1 = 0; g_c2 = 0; }
    if (t < 2) {
        int target = b + t;
        int lo = 0, hi = NN;
        while (lo < hi) { int mid = (lo + hi) >> 1; if (batch[mid] < target) lo = mid + 1; else hi = mid; }
        s_se[t] = lo;
    }
    __syncthreads();
    int start = s_se[0];
    int len = s_se[1] - start;

    int wid = t >> 5, lane = t & 31;
    float4 w = pw4[lane];
    // raw dot: one warp per node, unrolled x4 for memory-level parallelism
    int i = wid;
    for (; i + 24 < len; i += 32) {
        const float4* base = &x4[(size_t)(start + i) * 32 + lane];
        float4 v0 = base[0];
        float4 v1 = base[8 * 32];
        float4 v2 = base[16 * 32];
        float4 v3 = base[24 * 32];
        float s0 = v0.x * w.x + v0.y * w.y + v0.z * w.z + v0.w * w.w;
        float s1 = v1.x * w.x + v1.y * w.y + v1.z * w.z + v1.w * w.w;
        float s2 = v2.x * w.x + v2.y * w.y + v2.z * w.z + v2.w * w.w;
        float s3 = v3.x * w.x + v3.y * w.y + v3.z * w.z + v3.w * w.w;
        #pragma unroll
        for (int o = 16; o; o >>= 1) {
            s0 += __shfl_down_sync(0xffffffffu, s0, o);
            s1 += __shfl_down_sync(0xffffffffu, s1, o);
            s2 += __shfl_down_sync(0xffffffffu, s2, o);
            s3 += __shfl_down_sync(0xffffffffu, s3, o);
        }
        if (lane == 0) {
            sraw[i] = s0; sraw[i + 8] = s1; sraw[i + 16] = s2; sraw[i + 24] = s3;
        }
    }
    for (; i < len; i += 8) {
        float4 v = x4[(size_t)(start + i) * 32 + lane];
        float s = v.x * w.x + v.y * w.y + v.z * w.z + v.w * w.w;
        #pragma unroll
        for (int o = 16; o; o >>= 1) s += __shfl_down_sync(0xffffffffu, s, o);
        if (lane == 0) sraw[i] = s;
    }
    __syncthreads();

    float m = -INFINITY;
    for (int q = t; q < len; q += 256) m = fmaxf(m, sraw[q]);
    red[t] = m; __syncthreads();
    for (int o = 128; o; o >>= 1) { if (t < o) red[t] = fmaxf(red[t], red[t + o]); __syncthreads(); }
    m = red[0]; __syncthreads();

    float sum = 0.f;
    for (int q = t; q < len; q += 256) sum += expf(sraw[q] - m);
    red[t] = sum; __syncthreads();
    for (int o = 128; o; o >>= 1) { if (t < o) red[t] += red[t + o]; __syncthreads(); }
    float z = red[0]; __syncthreads();

    float smax = 1.0f / z;   // score of the argmax node (exp(0)/z)
    float thresh = fminf(smax - 1e-7f, 0.05f);

    float kl = 0.f, cnt = 0.f;
    for (int q = t; q < len; q += 256) {
        float s = expf(sraw[q] - m) / z;
        int node = start + q;
        if (s > thresh) {
            cnt += 1.f;
            float a = attn[node];
            kl += a * (logf(a) - logf(s + 1e-14f));
            g_score[node] = s;
            int slot = atomicAdd(&s_kcnt, 1);
            if (slot < KMAX) {
                g_kept[b * KMAX + slot] = node;
                atomicOr(&g_bits[node >> 5], 1u << (node & 31));
                float4 zz = make_float4(0.f, 0.f, 0.f, 0.f);
                float4* a1 = &g_agg1[(size_t)node * 32];
                #pragma unroll
                for (int qq = 0; qq < 32; qq++) a1[qq] = zz;
                float4* a2 = &g_agg2[(size_t)node * 16];
                #pragma unroll
                for (int qq = 0; qq < 16; qq++) a2[qq] = zz;
            }
        }
    }
    red[t] = kl; __syncthreads();
    for (int o = 128; o; o >>= 1) { if (t < o) red[t] += red[t + o]; __syncthreads(); }
    if (t == 0) g_klval[b] = red[0];
    __syncthreads();
    red[t] = cnt; __syncthreads();
    for (int o = 128; o; o >>= 1) { if (t < o) red[t] += red[t + o]; __syncthreads(); }
    if (t == 0) {
        g_cntval[b] = red[0];
        g_keptcnt[b] = (s_kcnt < KMAX) ? s_kcnt : KMAX;
    }
}

// ---------------- k_edges: scatter-1 + both-kept edge list + ratio ----------
#define EPB 1024
__global__ void k_edges(const int* __restrict__ ei, const float4* __restrict__ x4,
                        float* __restrict__ out) {
    __shared__ int list[EPB];
    __shared__ int scnt;
    __shared__ float rsum[256];
    if (threadIdx.x == 0) scnt = 0;
    __syncthreads();
    int q = blockIdx.x * 256 + threadIdx.x;
    if (q < EE / 4) {
        int4 d4 = ((const int4*)(ei + EE))[q];
        int e0 = q * 4;
        int dd[4] = {d4.x, d4.y, d4.z, d4.w};
        #pragma unroll
        for (int k = 0; k < 4; k++) {
            int d = dd[k];
            if (testbit(d)) {
                int e = e0 + k;
                int p = atomicAdd(&scnt, 1);
                list[p] = e;
                int s = ei[e];
                if (testbit(s)) {
                    int w = atomicAdd(&g_n2, 1);
                    g_elist[w] = e;
                }
            }
        }
    }
    __syncthreads();
    int nk = scnt;
    int wid = threadIdx.x >> 5;
    int lane = threadIdx.x & 31;
    for (int i = wid; i < nk; i += 8) {
        int ee = list[i];
        int s = ei[ee];
        int d = ei[EE + ee];
        red_add_v4(&g_agg1[(size_t)d * 32 + lane], x4[(size_t)s * 32 + lane]);
    }
    if (blockIdx.x == 0) {
        __syncthreads();
        rsum[threadIdx.x] = g_cntval[threadIdx.x] + g_cntval[threadIdx.x + 256];
        __syncthreads();
        for (int o = 128; o; o >>= 1) { if (threadIdx.x < o) rsum[threadIdx.x] += rsum[threadIdx.x + o]; __syncthreads(); }
        if (threadIdx.x == 0) out[2 * GG] = rsum[0] / (float)NN;
    }
}

// ---------------- k_tail: gin1 -> barrier -> scatter2 -> barrier -> gin2+out --
__global__ void __launch_bounds__(128, 4) k_tail(
    const float* __restrict__ x,
    const float* __restrict__ W1, const float* __restrict__ b1,
    const float* __restrict__ W2, const float* __restrict__ b2,
    const int* __restrict__ ei,
    const float* __restrict__ W3, const float* __restrict__ b3,
    const float* __restrict__ W4, const float* __restrict__ b4,
    const float* __restrict__ Wl, const float* __restrict__ bl,
    float* __restrict__ out)
{
    int g = blockIdx.x;
    int t = threadIdx.x;
    int j = t & 63;
    int h = t >> 6;       // k-half: 0 or 1
    __shared__ float sv[CC];
    __shared__ float sp[2][HH];
    __shared__ float sh1[HH];
    __shared__ float sgo[HH];
    int cnt = g_keptcnt[g];

    // ---- Phase 1: GIN1 for this graph's kept nodes ----
    for (int s = 0; s < cnt; s++) {
        int n = g_kept[g * KMAX + s];
        sv[t] = x[(size_t)n * CC + t] + ((const float*)g_agg1)[(size_t)n * CC + t];
        __syncthreads();
        float acc = (h == 0) ? b1[j] : 0.f;
        const float* wp = W1 + (size_t)(h * 64) * HH + j;
        #pragma unroll 8
        for (int k = 0; k < 64; k++) acc = fmaf(sv[h * 64 + k], wp[(size_t)k * HH], acc);
        sp[h][j] = acc;
        __syncthreads();
        if (t < HH) sh1[t] = fmaxf(sp[0][t] + sp[1][t], 0.f);
        __syncthreads();
        float acc2 = (h == 0) ? b2[j] : 0.f;
        const float* wp2 = W2 + (size_t)(h * 32) * HH + j;
        #pragma unroll 8
        for (int k = 0; k < 32; k++) acc2 = fmaf(sh1[h * 32 + k], wp2[(size_t)k * HH], acc2);
        sp[h][j] = acc2;
        __syncthreads();
        if (t < HH)
            ((float*)g_out1)[(size_t)n * HH + t] = fmaxf(sp[0][t] + sp[1][t], 0.f) * g_score[n];
        __syncthreads();
    }

    // ---- device-wide barrier 1 ----
    __threadfence();
    __syncthreads();
    if (t == 0) {
        atomicAdd(&g_c1, 1);
        while (atomicAdd(&g_c1, 0) < (int)gridDim.x) __nanosleep(64);
    }
    __syncthreads();

    // ---- Phase 2: scatter-2 over both-kept edges, spread across all blocks ----
    {
        int n2 = g_n2;
        int wid = t >> 5, lane = t & 31;
        for (int i = blockIdx.x * 4 + wid; i < n2; i += gridDim.x * 4) {
            int e = g_elist[i];
            int ss = ei[e];
            int dd = ei[EE + e];
            if (lane < 16) {
                float4 v = ldcg4(&g_out1[(size_t)ss * 16 + lane]);
                red_add_v4(&g_agg2[(size_t)dd * 16 + lane], v);
            }
        }
    }

    // ---- device-wide barrier 2 ----
    __threadfence();
    __syncthreads();
    if (t == 0) {
        atomicAdd(&g_c2, 1);
        while (atomicAdd(&g_c2, 0) < (int)gridDim.x) __nanosleep(64);
    }
    __syncthreads();

    // ---- Phase 3: GIN2 + global_add_pool + pred + attn_loss ----
    if (t < HH) sgo[t] = 0.f;
    __syncthreads();
    for (int s = 0; s < cnt; s++) {
        int n = g_kept[g * KMAX + s];
        if (t < HH)
            sv[t] = ldcg(&((const float*)g_out1)[(size_t)n * HH + t])
                  + ldcg(&((const float*)g_agg2)[(size_t)n * HH + t]);
        __syncthreads();
        float acc = (h == 0) ? b3[j] : 0.f;
        const float* wp = W3 + (size_t)(h * 32) * HH + j;
        #pragma unroll 8
        for (int k = 0; k < 32; k++) acc = fmaf(sv[h * 32 + k], wp[(size_t)k * HH], acc);
        sp[h][j] = acc;
        __syncthreads();
        if (t < HH) sh1[t] = fmaxf(sp[0][t] + sp[1][t], 0.f);
        __syncthreads();
        float acc2 = (h == 0) ? b4[j] : 0.f;
        const float* wp2 = W4 + (size_t)(h * 32) * HH + j;
        #pragma unroll 8
        for (int k = 0; k < 32; k++) acc2 = fmaf(sh1[h * 32 + k], wp2[(size_t)k * HH], acc2);
        sp[h][j] = acc2;
        __syncthreads();
        if (t < HH) sgo[t] += fmaxf(sp[0][t] + sp[1][t], 0.f);
        __syncthreads();
    }
    if (t < HH) sp[0][t] = sgo[t] * Wl[t];
    __syncthreads();
    if (t < 32) {
        float p = sp[0][t] + sp[0][t + 32];
        #pragma unroll
        for (int o = 16; o; o >>= 1) p += __shfl_down_sync(0xffffffffu, p, o);
        if (t == 0) {
            out[g] = p + bl[0];
            out[GG + g] = g_klval[g] / fmaxf(g_cntval[g], 1.0f);
        }
    }
    // self-clean: clear this graph's kept bits so g_bits is zero for the next call
    if (t < cnt) {
        int n = g_kept[g * KMAX + t];
        atomicAnd(&g_bits[n >> 5], ~(1u << (n & 31)));
    }
}

// ---------------- launch ----------------
extern "C" void kernel_launch(void* const* d_in, const int* in_sizes, int n_in,
                              void* d_out, int out_size) {
    const float* x      = (const float*)d_in[0];
    const int*   ei     = (const int*)d_in[1];
    const int*   batch  = (const int*)d_in[2];
    const float* attn   = (const float*)d_in[3];
    const float* W1     = (const float*)d_in[4];
    const float* b1     = (const float*)d_in[5];
    const float* W2     = (const float*)d_in[6];
    const float* b2     = (const float*)d_in[7];
    const float* pool_w = (const float*)d_in[8];
    const float* W3     = (const float*)d_in[9];
    const float* b3     = (const float*)d_in[10];
    const float* W4     = (const float*)d_in[11];
    const float* b4     = (const float*)d_in[12];
    const float* Wl     = (const float*)d_in[13];
    const float* bl     = (const float*)d_in[14];
    float* out = (float*)d_out;

    k_pool<<<GG, 256>>>((const float4*)x, (const float4*)pool_w, batch, attn);
    k_edges<<<(EE + EPB - 1) / EPB, 256>>>(ei, (const float4*)x, out);
    k_tail<<<GG, 128>>>(x, W1, b1, W2, b2, ei, W3, b3, W4, b4, Wl, bl, out);
}